// round 8
// baseline (speedup 1.0000x reference)
#include <cuda_runtime.h>

#define T_STEPS 512
#define BATCH   64
#define IDIM    128
#define HDIM    512
#define ZDIM    32
#define GRID_MAIN 128
#define ALPHA 0.2f
#define ONEMA 0.8f

typedef unsigned long long ull;

// ---------------- device scratch (static globals; no runtime allocation) ----
__device__ float g_xin [(size_t)T_STEPS * HDIM * BATCH];        // (t, g, b)
__device__ float g_rbuf[(size_t)(T_STEPS + 1) * HDIM * BATCH];  // (t, h, b)
__device__ float g_xz  [(size_t)T_STEPS * BATCH * ZDIM];        // (t, b, z)
__device__ float g_sbuf[(size_t)T_STEPS * BATCH * 2];           // (t, b, k): s-0.5
__device__ unsigned long long g_bar;                            // monotonic barrier

// ---------------- helpers ---------------------------------------------------
__device__ __forceinline__ unsigned smem_u32(const void* p) {
    return (unsigned)__cvta_generic_to_shared(p);
}
__device__ __forceinline__ void cp16(unsigned dst, const void* src) {
    asm volatile("cp.async.cg.shared.global [%0], [%1], 16;" :: "r"(dst), "l"(src));
}
__device__ __forceinline__ void cp_commit() {
    asm volatile("cp.async.commit_group;");
}
template <int N>
__device__ __forceinline__ void cp_wait() {
    asm volatile("cp.async.wait_group %0;" :: "n"(N));
}
// packed fp32x2 math (sm_100+)
__device__ __forceinline__ ull ffma2(ull a, ull b, ull c) {
    ull d; asm("fma.rn.f32x2 %0,%1,%2,%3;" : "=l"(d) : "l"(a), "l"(b), "l"(c)); return d;
}
__device__ __forceinline__ ull fmul2(ull a, ull b) {
    ull d; asm("mul.rn.f32x2 %0,%1,%2;" : "=l"(d) : "l"(a), "l"(b)); return d;
}
__device__ __forceinline__ ull fadd2(ull a, ull b) {
    ull d; asm("add.rn.f32x2 %0,%1,%2;" : "=l"(d) : "l"(a), "l"(b)); return d;
}
__device__ __forceinline__ ull dup2(float x) {
    ull d; asm("mov.b64 %0,{%1,%1};" : "=l"(d) : "f"(x)); return d;
}

// Replay-safe grid barrier: monotonic counter, target derived from arrival slot.
__device__ __forceinline__ void grid_barrier() {
    __syncthreads();
    if (threadIdx.x == 0) {
        __threadfence();
        unsigned long long a = atomicAdd(&g_bar, 1ULL);
        unsigned long long target = (a / GRID_MAIN + 1ULL) * (unsigned long long)GRID_MAIN;
        unsigned long long cur;
        do {
            asm volatile("ld.global.acquire.gpu.u64 %0, [%1];" : "=l"(cur) : "l"(&g_bar));
        } while (cur < target);
    }
    __syncthreads();
}

// ---------------- k_xin: xin[t,g,b] = sum_i x[b,t,i]*W_in[g,i] + b_rec[g] ----
__global__ void __launch_bounds__(128, 1) k_xin(const float* __restrict__ x,
                                                const float* __restrict__ win,
                                                const float* __restrict__ brec) {
    extern __shared__ float sm[];
    float* x_s = sm;         // [i][b]
    float* w_s = sm + 8192;  // [i][gl]
    const int tid = threadIdx.x;
    const int t   = blockIdx.x;
    const int g0  = blockIdx.y * 64;

    for (int idx = tid; idx < 8192; idx += 128) {
        int b = idx >> 7, i = idx & 127;
        x_s[i * 64 + b] = x[(size_t)b * (T_STEPS * IDIM) + t * IDIM + i];
    }
    for (int idx = tid; idx < 8192; idx += 128) {
        int gl = idx >> 7, i = idx & 127;
        w_s[i * 64 + gl] = win[(g0 + gl) * IDIM + i];
    }
    __syncthreads();

    const int gt = tid >> 3;   // 16 groups of 4 g
    const int bt = tid & 7;    // 8 groups of 8 b (4 packed pairs)
    ull acc[4][4];
#pragma unroll
    for (int a = 0; a < 4; ++a)
#pragma unroll
        for (int j = 0; j < 4; ++j) acc[a][j] = 0ULL;

    const float4* wp = (const float4*)w_s + gt;
    const ull* xp = (const ull*)x_s + bt * 4;
#pragma unroll 4
    for (int i = 0; i < 128; ++i) {
        float4 wv = wp[i * 16];
        ull x0 = xp[i * 32], x1 = xp[i * 32 + 1], x2 = xp[i * 32 + 2], x3 = xp[i * 32 + 3];
        ull w0 = dup2(wv.x), w1 = dup2(wv.y), w2 = dup2(wv.z), w3 = dup2(wv.w);
        acc[0][0] = ffma2(w0, x0, acc[0][0]); acc[0][1] = ffma2(w0, x1, acc[0][1]);
        acc[0][2] = ffma2(w0, x2, acc[0][2]); acc[0][3] = ffma2(w0, x3, acc[0][3]);
        acc[1][0] = ffma2(w1, x0, acc[1][0]); acc[1][1] = ffma2(w1, x1, acc[1][1]);
        acc[1][2] = ffma2(w1, x2, acc[1][2]); acc[1][3] = ffma2(w1, x3, acc[1][3]);
        acc[2][0] = ffma2(w2, x0, acc[2][0]); acc[2][1] = ffma2(w2, x1, acc[2][1]);
        acc[2][2] = ffma2(w2, x2, acc[2][2]); acc[2][3] = ffma2(w2, x3, acc[2][3]);
        acc[3][0] = ffma2(w3, x0, acc[3][0]); acc[3][1] = ffma2(w3, x1, acc[3][1]);
        acc[3][2] = ffma2(w3, x2, acc[3][2]); acc[3][3] = ffma2(w3, x3, acc[3][3]);
    }
#pragma unroll
    for (int a = 0; a < 4; ++a) {
        int g = g0 + gt * 4 + a;
        ull bias = dup2(brec[g]);
        ull* op = (ull*)(g_xin + (size_t)t * (HDIM * BATCH) + g * BATCH + bt * 8);
#pragma unroll
        for (int j = 0; j < 4; ++j) op[j] = fadd2(acc[a][j], bias);
    }
}

// ---------------- k_xz: xz[t,b,z] = sum_i x[b,t,i]*B_z[z,i] + b_zz[z] -------
__global__ void __launch_bounds__(64, 1) k_xz(const float* __restrict__ x,
                                              const float* __restrict__ Bz,
                                              const float* __restrict__ bzz) {
    extern __shared__ float sm[];
    float* x_s  = sm;         // [i][b]
    float* bz_s = sm + 8192;  // [i][z]
    const int tid = threadIdx.x;
    const int t   = blockIdx.x;

    for (int idx = tid; idx < 8192; idx += 64) {
        int b = idx >> 7, i = idx & 127;
        x_s[i * 64 + b] = x[(size_t)b * (T_STEPS * IDIM) + t * IDIM + i];
    }
    for (int idx = tid; idx < 4096; idx += 64) {
        int z = idx >> 7, i = idx & 127;
        bz_s[i * 32 + z] = Bz[z * IDIM + i];
    }
    __syncthreads();

    const int zt = tid >> 3;
    const int bt = tid & 7;
    float acc[4][8];
#pragma unroll
    for (int a = 0; a < 4; ++a)
#pragma unroll
        for (int j = 0; j < 8; ++j) acc[a][j] = 0.f;

    const float4* wp = (const float4*)bz_s + zt;
    const float4* xp = (const float4*)x_s + bt * 2;
#pragma unroll 4
    for (int i = 0; i < 128; ++i) {
        float4 wv = wp[i * 8];
        float4 xa = xp[i * 16];
        float4 xb = xp[i * 16 + 1];
        float xv[8] = {xa.x, xa.y, xa.z, xa.w, xb.x, xb.y, xb.z, xb.w};
#pragma unroll
        for (int j = 0; j < 8; ++j) {
            acc[0][j] = fmaf(wv.x, xv[j], acc[0][j]);
            acc[1][j] = fmaf(wv.y, xv[j], acc[1][j]);
            acc[2][j] = fmaf(wv.z, xv[j], acc[2][j]);
            acc[3][j] = fmaf(wv.w, xv[j], acc[3][j]);
        }
    }
#pragma unroll
    for (int a = 0; a < 4; ++a) {
        int z = zt * 4 + a;
        float bias = bzz[z];
#pragma unroll
        for (int j = 0; j < 8; ++j) {
            int b = bt * 8 + j;
            g_xz[(size_t)t * (BATCH * ZDIM) + b * ZDIM + z] = acc[a][j] + bias;
        }
    }
}

// ---------------- k_zscan: sequential z recursion, emits (s-0.5) ------------
__global__ void k_zscan(const float* __restrict__ Wzz,
                        const float* __restrict__ M,
                        const float* __restrict__ c,
                        float* __restrict__ dout, int out_size) {
    __shared__ float wzz_s[ZDIM * ZDIM];  // transposed [j][i]
    __shared__ float fzs[ZDIM];
    const int i = threadIdx.x;
    const int b = blockIdx.x;

    for (int idx = i; idx < ZDIM * ZDIM; idx += 32) {
        int is = idx >> 5, j = idx & 31;
        wzz_s[j * 32 + is] = Wzz[idx];
    }
    float m0 = M[i], m1 = M[ZDIM + i];
    float c0 = c[0], c1 = c[1];
    float z = 0.f;
    __syncwarp();

    for (int t = 0; t < T_STEPS; ++t) {
        fzs[i] = tanhf(z);
        __syncwarp();
        // 4-way partial chains: dependency depth 8 FMAs instead of 32
        float a0 = 0.f, a1 = 0.f, a2 = 0.f, a3 = 0.f;
#pragma unroll
        for (int j = 0; j < 32; j += 4) {
            a0 = fmaf(wzz_s[(j + 0) * 32 + i], fzs[j + 0], a0);
            a1 = fmaf(wzz_s[(j + 1) * 32 + i], fzs[j + 1], a1);
            a2 = fmaf(wzz_s[(j + 2) * 32 + i], fzs[j + 2], a2);
            a3 = fmaf(wzz_s[(j + 3) * 32 + i], fzs[j + 3], a3);
        }
        float a = (a0 + a1) + (a2 + a3);
        __syncwarp();
        z = ONEMA * z + ALPHA * (a + g_xz[(size_t)t * (BATCH * ZDIM) + b * ZDIM + i]);
        float p0 = m0 * z, p1 = m1 * z;
#pragma unroll
        for (int off = 16; off; off >>= 1) {
            p0 += __shfl_xor_sync(0xffffffffu, p0, off);
            p1 += __shfl_xor_sync(0xffffffffu, p1, off);
        }
        if (i == 0) {
            size_t o = ((size_t)t * BATCH + b) * 2;
            g_sbuf[o + 0] = 1.f / (1.f + expf(-(p0 + c0))) - 0.5f;
            g_sbuf[o + 1] = 1.f / (1.f + expf(-(p1 + c1))) - 0.5f;
        }
    }
    if (out_size >= BATCH * T_STEPS + BATCH * HDIM + BATCH * ZDIM)
        dout[BATCH * T_STEPS + BATCH * HDIM + b * ZDIM + i] = z;  // zT
}

// ---------------- k_main: persistent recurrent core -------------------------
// grid 128, 256 threads (8 warps), dyn smem = 43008 floats (172,032 B)
// Warp sl owns h-rows {h : h % 8 == sl} (64 rows): it cp.asyncs ONLY those rows
// and computes on them — no __syncthreads in the mainloop, only per-warp
// cp.async.wait + __syncwarp. One __syncthreads before the partial reduction.
// SMEM: r_s[512h][64b] | wd[512h][8] (w0..w3,v0,v1,pad2) | part[8 sl][12 row][64 b]
__global__ void __launch_bounds__(256, 1) k_main(const float* __restrict__ W,
                                                 const float* __restrict__ V,
                                                 const float* __restrict__ U,
                                                 float* __restrict__ dout,
                                                 int out_size) {
    extern __shared__ float sm[];
    float* r_s  = sm;            // 32768
    float* wd   = sm + 32768;    // 4096
    float* part = sm + 36864;    // 6144
    const int tid = threadIdx.x;
    const int g0  = blockIdx.x * 4;

    // stage weights (un-dup'd): per h {w0,w1,w2,w3,v0,v1,pad,pad}
#pragma unroll 2
    for (int h = tid; h < HDIM; h += 256) {
        float* p = wd + h * 8;
        p[0] = W[(g0 + 0) * HDIM + h];
        p[1] = W[(g0 + 1) * HDIM + h];
        p[2] = W[(g0 + 2) * HDIM + h];
        p[3] = W[(g0 + 3) * HDIM + h];
        p[4] = V[h * 2 + 0];
        p[5] = V[h * 2 + 1];
        p[6] = 0.f; p[7] = 0.f;
    }
    const int eg = tid >> 6;  // epilogue g 0..3
    const int eb = tid & 63;  // epilogue b
    const float u0 = U[(g0 + eg) * 2 + 0];
    const float u1 = U[(g0 + eg) * 2 + 1];
    float v = 0.f;
    g_rbuf[(size_t)(g0 + eg) * BATCH + eb] = 0.f;  // r_0 = tanh(0)
    grid_barrier();

    const int sl   = tid >> 5;   // warp id 0..7 = h-slice
    const int lane = tid & 31;
    const int krow = lane >> 1;  // row-within-chunk 0..15
    const int half = lane & 1;   // 128B half of the 256B row
    const unsigned rbase = smem_u32(r_s);
    // per-warp cp addressing: row k (0..63) -> h = k*8 + sl, byte = h*256
    const unsigned cp_off0 = (unsigned)((krow * 8 + sl) * 256 + half * 128);
    const float* rp = r_s + sl * 64 + lane * 2;  // + k*512 floats
    const float* wp = wd + sl * 8;               // + k*64 floats

    for (int t = 0; t < T_STEPS; ++t) {
        const char* rg = (const char*)(g_rbuf + (size_t)t * (HDIM * BATCH));
        // issue all 4 chunks of our warp's 64 rows (16KB), 4KB per commit group
#pragma unroll
        for (int c = 0; c < 4; ++c) {
            unsigned off = cp_off0 + (unsigned)c * (16 * 2048);
#pragma unroll
            for (int j = 0; j < 8; ++j)
                cp16(rbase + off + j * 16, rg + off + j * 16);
            cp_commit();
        }
        // per-step scalars (L2 latency hidden behind chunk-0 wait)
        const float xi = __ldg(&g_xin[(size_t)t * (HDIM * BATCH) + (g0 + eg) * BATCH + eb]);
        const float* sp = g_sbuf + ((size_t)t * BATCH + eb) * 2;
        const float s0 = __ldg(sp), s1 = __ldg(sp + 1);

        ull acc[12];
#pragma unroll
        for (int m = 0; m < 12; ++m) acc[m] = 0ULL;

#pragma unroll
        for (int c = 0; c < 4; ++c) {
            if (c == 0) cp_wait<3>();
            else if (c == 1) cp_wait<2>();
            else if (c == 2) cp_wait<1>();
            else cp_wait<0>();
            __syncwarp();
#pragma unroll 4
            for (int i = 0; i < 16; ++i) {
                const int k = c * 16 + i;
                const float4 w4 = *(const float4*)(wp + k * 64);
                const float2 vv = *(const float2*)(wp + k * 64 + 4);
                const ull r = *(const ull*)(rp + k * 512);
                const ull w0d = dup2(w4.x), w1d = dup2(w4.y);
                const ull w2d = dup2(w4.z), w3d = dup2(w4.w);
                const ull rv0 = fmul2(dup2(vv.x), r);
                const ull rv1 = fmul2(dup2(vv.y), r);
                acc[0]  = ffma2(w0d, r,   acc[0]);
                acc[1]  = ffma2(w0d, rv0, acc[1]);
                acc[2]  = ffma2(w0d, rv1, acc[2]);
                acc[3]  = ffma2(w1d, r,   acc[3]);
                acc[4]  = ffma2(w1d, rv0, acc[4]);
                acc[5]  = ffma2(w1d, rv1, acc[5]);
                acc[6]  = ffma2(w2d, r,   acc[6]);
                acc[7]  = ffma2(w2d, rv0, acc[7]);
                acc[8]  = ffma2(w2d, rv1, acc[8]);
                acc[9]  = ffma2(w3d, r,   acc[9]);
                acc[10] = ffma2(w3d, rv0, acc[10]);
                acc[11] = ffma2(w3d, rv1, acc[11]);
            }
        }

        // partials: part[sl][row][b]
        {
            float* pb = part + sl * 768 + lane * 2;
#pragma unroll
            for (int row = 0; row < 12; ++row) *(ull*)(pb + row * 64) = acc[row];
        }
        __syncthreads();

        // epilogue: each of 256 threads reduces 8 slices for its (g, b) directly
        {
            float y0 = 0.f, y1 = 0.f, y2 = 0.f;
            const float* q = part + eg * 192 + eb;
#pragma unroll
            for (int s = 0; s < 8; ++s) {
                y0 += q[s * 768];
                y1 += q[s * 768 + 64];
                y2 += q[s * 768 + 128];
            }
            v = ONEMA * v + ALPHA * (y0 + s0 * u0 * y1 + s1 * u1 * y2 + xi);
            const float r = tanhf(v);
            g_rbuf[(size_t)(t + 1) * (HDIM * BATCH) + (g0 + eg) * BATCH + eb] = r;
            if (t == T_STEPS - 1 && out_size >= BATCH * T_STEPS + BATCH * HDIM)
                dout[BATCH * T_STEPS + eb * HDIM + (g0 + eg)] = v;  // vT
        }
        grid_barrier();
    }
}

// ---------------- k_out: y[b,t] = tanh(v_{t+1}) @ w_out + b_out -------------
__global__ void __launch_bounds__(256, 1) k_out(const float* __restrict__ wout,
                                                const float* __restrict__ bout,
                                                float* __restrict__ dout,
                                                int out_size) {
    __shared__ float w_sh[HDIM];
    const int tid = threadIdx.x;
    w_sh[tid] = wout[tid];
    w_sh[tid + 256] = wout[tid + 256];
    __syncthreads();
    int gid = blockIdx.x * 256 + tid;
    int b = gid & 63, t = gid >> 6;
    const float* rp = g_rbuf + (size_t)(t + 1) * (HDIM * BATCH) + b;
    float acc = bout[0];
#pragma unroll 8
    for (int g = 0; g < HDIM; ++g) acc = fmaf(rp[g * BATCH], w_sh[g], acc);
    int o = b * T_STEPS + t;
    if (o < out_size) dout[o] = acc;
}

// ---------------- launch -----------------------------------------------------
extern "C" void kernel_launch(void* const* d_in, const int* in_sizes, int n_in,
                              void* d_out, int out_size) {
    const float* x    = (const float*)d_in[0];
    const float* win  = (const float*)d_in[1];
    const float* wrec = (const float*)d_in[2];
    const float* brec = (const float*)d_in[3];
    const float* wout = (const float*)d_in[4];
    const float* bout = (const float*)d_in[5];
    const float* wzz  = (const float*)d_in[6];
    const float* bzz  = (const float*)d_in[7];
    const float* Bz   = (const float*)d_in[8];
    const float* M    = (const float*)d_in[9];
    const float* c    = (const float*)d_in[10];
    const float* U    = (const float*)d_in[11];
    const float* V    = (const float*)d_in[12];
    float* out = (float*)d_out;

    cudaFuncSetAttribute(k_xin,  cudaFuncAttributeMaxDynamicSharedMemorySize, 16384 * 4);
    cudaFuncSetAttribute(k_xz,   cudaFuncAttributeMaxDynamicSharedMemorySize, 12288 * 4);
    cudaFuncSetAttribute(k_main, cudaFuncAttributeMaxDynamicSharedMemorySize, 43008 * 4);

    k_xz<<<T_STEPS, 64, 12288 * 4>>>(x, Bz, bzz);
    k_zscan<<<BATCH, 32>>>(wzz, M, c, out, out_size);
    k_xin<<<dim3(T_STEPS, HDIM / 64), 128, 16384 * 4>>>(x, win, brec);
    k_main<<<GRID_MAIN, 256, 43008 * 4>>>(wrec, V, U, out, out_size);
    k_out<<<(BATCH * T_STEPS) / 256, 256>>>(wout, bout, out, out_size);
}

// round 9
// speedup vs baseline: 1.6729x; 1.6729x over previous
#include <cuda_runtime.h>

#define T_STEPS 512
#define BATCH   64
#define IDIM    128
#define HDIM    512
#define ZDIM    32
#define GRID_MAIN 128
#define ALPHA 0.2f
#define ONEMA 0.8f

typedef unsigned long long ull;

// ---------------- device scratch (static globals; no runtime allocation) ----
__device__ float g_xin [(size_t)T_STEPS * HDIM * BATCH];        // (t, g, b)
__device__ float g_rbuf[(size_t)(T_STEPS + 1) * HDIM * BATCH];  // (t, h, b)
__device__ float g_xz  [(size_t)T_STEPS * BATCH * ZDIM];        // (t, b, z)
__device__ float g_sbuf[(size_t)T_STEPS * BATCH * 2];           // (t, b, k): s-0.5
__device__ ull g_lo[8];                                         // barrier: low tier
__device__ ull g_hi;                                            // barrier: high tier

// ---------------- helpers ---------------------------------------------------
// packed fp32x2 math (sm_100+)
__device__ __forceinline__ ull ffma2(ull a, ull b, ull c) {
    ull d; asm("fma.rn.f32x2 %0,%1,%2,%3;" : "=l"(d) : "l"(a), "l"(b), "l"(c)); return d;
}
__device__ __forceinline__ ull fmul2(ull a, ull b) {
    ull d; asm("mul.rn.f32x2 %0,%1,%2;" : "=l"(d) : "l"(a), "l"(b)); return d;
}
__device__ __forceinline__ ull fadd2(ull a, ull b) {
    ull d; asm("add.rn.f32x2 %0,%1,%2;" : "=l"(d) : "l"(a), "l"(b)); return d;
}
__device__ __forceinline__ ull dup2(float x) {
    ull d; asm("mov.b64 %0,{%1,%1};" : "=l"(d) : "f"(x)); return d;
}
__device__ __forceinline__ ull ldg64cg(const float* p) {
    ull d; asm volatile("ld.global.cg.b64 %0, [%1];" : "=l"(d) : "l"(p)); return d;
}

// Hierarchical replay-safe grid barrier: 8 low counters (16 CTAs each) feed one
// high counter (8 arrivals/step). Monotonic; targets derived from arrival slot.
__device__ __forceinline__ void grid_barrier() {
    __syncthreads();
    if (threadIdx.x == 0) {
        __threadfence();  // release this CTA's r/global writes
        ull a = atomicAdd(&g_lo[blockIdx.x & 7], 1ULL);
        if ((a & 15ULL) == 15ULL) {       // last of this group this step
            __threadfence();
            atomicAdd(&g_hi, 1ULL);
        }
        const ull target = ((a >> 4) + 1ULL) * 8ULL;
        ull cur;
        do {
            asm volatile("ld.global.acquire.gpu.u64 %0, [%1];" : "=l"(cur) : "l"(&g_hi));
        } while (cur < target);
    }
    __syncthreads();
}

// ---------------- k_xin: xin[t,g,b] = sum_i x[b,t,i]*W_in[g,i] + b_rec[g] ----
__global__ void __launch_bounds__(128, 1) k_xin(const float* __restrict__ x,
                                                const float* __restrict__ win,
                                                const float* __restrict__ brec) {
    extern __shared__ float sm[];
    float* x_s = sm;         // [i][b]
    float* w_s = sm + 8192;  // [i][gl]
    const int tid = threadIdx.x;
    const int t   = blockIdx.x;
    const int g0  = blockIdx.y * 64;

    for (int idx = tid; idx < 8192; idx += 128) {
        int b = idx >> 7, i = idx & 127;
        x_s[i * 64 + b] = x[(size_t)b * (T_STEPS * IDIM) + t * IDIM + i];
    }
    for (int idx = tid; idx < 8192; idx += 128) {
        int gl = idx >> 7, i = idx & 127;
        w_s[i * 64 + gl] = win[(g0 + gl) * IDIM + i];
    }
    __syncthreads();

    const int gt = tid >> 3;
    const int bt = tid & 7;
    ull acc[4][4];
#pragma unroll
    for (int a = 0; a < 4; ++a)
#pragma unroll
        for (int j = 0; j < 4; ++j) acc[a][j] = 0ULL;

    const float4* wp = (const float4*)w_s + gt;
    const ull* xp = (const ull*)x_s + bt * 4;
#pragma unroll 4
    for (int i = 0; i < 128; ++i) {
        float4 wv = wp[i * 16];
        ull x0 = xp[i * 32], x1 = xp[i * 32 + 1], x2 = xp[i * 32 + 2], x3 = xp[i * 32 + 3];
        ull w0 = dup2(wv.x), w1 = dup2(wv.y), w2 = dup2(wv.z), w3 = dup2(wv.w);
        acc[0][0] = ffma2(w0, x0, acc[0][0]); acc[0][1] = ffma2(w0, x1, acc[0][1]);
        acc[0][2] = ffma2(w0, x2, acc[0][2]); acc[0][3] = ffma2(w0, x3, acc[0][3]);
        acc[1][0] = ffma2(w1, x0, acc[1][0]); acc[1][1] = ffma2(w1, x1, acc[1][1]);
        acc[1][2] = ffma2(w1, x2, acc[1][2]); acc[1][3] = ffma2(w1, x3, acc[1][3]);
        acc[2][0] = ffma2(w2, x0, acc[2][0]); acc[2][1] = ffma2(w2, x1, acc[2][1]);
        acc[2][2] = ffma2(w2, x2, acc[2][2]); acc[2][3] = ffma2(w2, x3, acc[2][3]);
        acc[3][0] = ffma2(w3, x0, acc[3][0]); acc[3][1] = ffma2(w3, x1, acc[3][1]);
        acc[3][2] = ffma2(w3, x2, acc[3][2]); acc[3][3] = ffma2(w3, x3, acc[3][3]);
    }
#pragma unroll
    for (int a = 0; a < 4; ++a) {
        int g = g0 + gt * 4 + a;
        ull bias = dup2(brec[g]);
        ull* op = (ull*)(g_xin + (size_t)t * (HDIM * BATCH) + g * BATCH + bt * 8);
#pragma unroll
        for (int j = 0; j < 4; ++j) op[j] = fadd2(acc[a][j], bias);
    }
}

// ---------------- k_xz: xz[t,b,z] = sum_i x[b,t,i]*B_z[z,i] + b_zz[z] -------
__global__ void __launch_bounds__(64, 1) k_xz(const float* __restrict__ x,
                                              const float* __restrict__ Bz,
                                              const float* __restrict__ bzz) {
    extern __shared__ float sm[];
    float* x_s  = sm;         // [i][b]
    float* bz_s = sm + 8192;  // [i][z]
    const int tid = threadIdx.x;
    const int t   = blockIdx.x;

    for (int idx = tid; idx < 8192; idx += 64) {
        int b = idx >> 7, i = idx & 127;
        x_s[i * 64 + b] = x[(size_t)b * (T_STEPS * IDIM) + t * IDIM + i];
    }
    for (int idx = tid; idx < 4096; idx += 64) {
        int z = idx >> 7, i = idx & 127;
        bz_s[i * 32 + z] = Bz[z * IDIM + i];
    }
    __syncthreads();

    const int zt = tid >> 3;
    const int bt = tid & 7;
    float acc[4][8];
#pragma unroll
    for (int a = 0; a < 4; ++a)
#pragma unroll
        for (int j = 0; j < 8; ++j) acc[a][j] = 0.f;

    const float4* wp = (const float4*)bz_s + zt;
    const float4* xp = (const float4*)x_s + bt * 2;
#pragma unroll 4
    for (int i = 0; i < 128; ++i) {
        float4 wv = wp[i * 8];
        float4 xa = xp[i * 16];
        float4 xb = xp[i * 16 + 1];
        float xv[8] = {xa.x, xa.y, xa.z, xa.w, xb.x, xb.y, xb.z, xb.w};
#pragma unroll
        for (int j = 0; j < 8; ++j) {
            acc[0][j] = fmaf(wv.x, xv[j], acc[0][j]);
            acc[1][j] = fmaf(wv.y, xv[j], acc[1][j]);
            acc[2][j] = fmaf(wv.z, xv[j], acc[2][j]);
            acc[3][j] = fmaf(wv.w, xv[j], acc[3][j]);
        }
    }
#pragma unroll
    for (int a = 0; a < 4; ++a) {
        int z = zt * 4 + a;
        float bias = bzz[z];
#pragma unroll
        for (int j = 0; j < 8; ++j) {
            int b = bt * 8 + j;
            g_xz[(size_t)t * (BATCH * ZDIM) + b * ZDIM + z] = acc[a][j] + bias;
        }
    }
}

// ---------------- k_zscan: sequential z recursion, emits (s-0.5) ------------
__global__ void k_zscan(const float* __restrict__ Wzz,
                        const float* __restrict__ M,
                        const float* __restrict__ c,
                        float* __restrict__ dout, int out_size) {
    __shared__ float wzz_s[ZDIM * ZDIM];  // transposed [j][i]
    __shared__ float fzs[ZDIM];
    const int i = threadIdx.x;
    const int b = blockIdx.x;

    for (int idx = i; idx < ZDIM * ZDIM; idx += 32) {
        int is = idx >> 5, j = idx & 31;
        wzz_s[j * 32 + is] = Wzz[idx];
    }
    float m0 = M[i], m1 = M[ZDIM + i];
    float c0 = c[0], c1 = c[1];
    float z = 0.f;
    __syncwarp();

    for (int t = 0; t < T_STEPS; ++t) {
        fzs[i] = tanhf(z);
        __syncwarp();
        float a0 = 0.f, a1 = 0.f, a2 = 0.f, a3 = 0.f;
#pragma unroll
        for (int j = 0; j < 32; j += 4) {
            a0 = fmaf(wzz_s[(j + 0) * 32 + i], fzs[j + 0], a0);
            a1 = fmaf(wzz_s[(j + 1) * 32 + i], fzs[j + 1], a1);
            a2 = fmaf(wzz_s[(j + 2) * 32 + i], fzs[j + 2], a2);
            a3 = fmaf(wzz_s[(j + 3) * 32 + i], fzs[j + 3], a3);
        }
        float a = (a0 + a1) + (a2 + a3);
        __syncwarp();
        z = ONEMA * z + ALPHA * (a + g_xz[(size_t)t * (BATCH * ZDIM) + b * ZDIM + i]);
        float p0 = m0 * z, p1 = m1 * z;
#pragma unroll
        for (int off = 16; off; off >>= 1) {
            p0 += __shfl_xor_sync(0xffffffffu, p0, off);
            p1 += __shfl_xor_sync(0xffffffffu, p1, off);
        }
        if (i == 0) {
            size_t o = ((size_t)t * BATCH + b) * 2;
            g_sbuf[o + 0] = 1.f / (1.f + expf(-(p0 + c0))) - 0.5f;
            g_sbuf[o + 1] = 1.f / (1.f + expf(-(p1 + c1))) - 0.5f;
        }
    }
    if (out_size >= BATCH * T_STEPS + BATCH * HDIM + BATCH * ZDIM)
        dout[BATCH * T_STEPS + BATCH * HDIM + b * ZDIM + i] = z;  // zT
}

// ---------------- k_main: persistent recurrent core -------------------------
// grid 128, 512 threads (16 warps), dyn smem = 16384 floats (65,536 B)
// No SMEM staging of r: each r element is consumed by exactly ONE thread, so
// the mainloop reads r_t straight from L2 via ld.global.cg with a depth-1
// register pipeline (groups of 4 h). Zero __syncthreads in the mainloop.
// Thread (sl = warp 0..15, bg = lane 0..31) owns h in {k*16+sl} (32 rows) and
// the batch pair {2bg, 2bg+1}.
// SMEM: wd[512h][8] (w0..w3,v0,v1,pad2) | part[16 sl][12 row][64 b]
__global__ void __launch_bounds__(512, 1) k_main(const float* __restrict__ W,
                                                 const float* __restrict__ V,
                                                 const float* __restrict__ U,
                                                 float* __restrict__ dout,
                                                 int out_size) {
    extern __shared__ float sm[];
    float* wd   = sm;          // 4096 floats
    float* part = sm + 4096;   // 12288 floats
    const int tid = threadIdx.x;
    const int g0  = blockIdx.x * 4;

    // stage weights: per h {w0,w1,w2,w3,v0,v1,pad,pad}
    {
        const int h = tid;  // 512 threads = 512 h
        float* p = wd + h * 8;
        p[0] = W[(g0 + 0) * HDIM + h];
        p[1] = W[(g0 + 1) * HDIM + h];
        p[2] = W[(g0 + 2) * HDIM + h];
        p[3] = W[(g0 + 3) * HDIM + h];
        p[4] = V[h * 2 + 0];
        p[5] = V[h * 2 + 1];
        p[6] = 0.f; p[7] = 0.f;
    }
    const int eg = tid >> 6;  // epilogue g (tid < 256)
    const int eb = tid & 63;
    float u0 = 0.f, u1 = 0.f, v = 0.f;
    if (tid < 256) {
        u0 = U[(g0 + eg) * 2 + 0];
        u1 = U[(g0 + eg) * 2 + 1];
        g_rbuf[(size_t)(g0 + eg) * BATCH + eb] = 0.f;  // r_0 = tanh(0)
    }
    grid_barrier();

    const int sl   = tid >> 5;  // warp id = h-slice
    const int lane = tid & 31;  // batch pair {2*lane, 2*lane+1}
    // h(k) = k*16 + sl  ->  r offset = h*64 + lane*2 = k*1024 + sl*64 + lane*2
    const int roff = sl * 64 + lane * 2;
    const float* wp0 = wd + sl * 8;  // + k*128 floats

    for (int t = 0; t < T_STEPS; ++t) {
        const float* rg = g_rbuf + (size_t)t * (HDIM * BATCH) + roff;

        ull rb0[4], rb1[4];
#pragma unroll
        for (int j = 0; j < 4; ++j) rb0[j] = ldg64cg(rg + j * 1024);

        // per-step scalars (latency hidden behind mainloop)
        float xi = 0.f, s0 = 0.f, s1 = 0.f;
        if (tid < 256) {
            xi = __ldg(&g_xin[(size_t)t * (HDIM * BATCH) + (g0 + eg) * BATCH + eb]);
            const float* sp = g_sbuf + ((size_t)t * BATCH + eb) * 2;
            s0 = __ldg(sp); s1 = __ldg(sp + 1);
        }

        ull acc[12];
#pragma unroll
        for (int m = 0; m < 12; ++m) acc[m] = 0ULL;

#pragma unroll
        for (int kg = 0; kg < 8; ++kg) {
            ull* cur = (kg & 1) ? rb1 : rb0;
            ull* nxt = (kg & 1) ? rb0 : rb1;
            if (kg < 7) {
#pragma unroll
                for (int j = 0; j < 4; ++j)
                    nxt[j] = ldg64cg(rg + (kg * 4 + 4 + j) * 1024);
            }
#pragma unroll
            for (int j = 0; j < 4; ++j) {
                const int k = kg * 4 + j;
                const float4 w4 = *(const float4*)(wp0 + k * 128);
                const float2 vv = *(const float2*)(wp0 + k * 128 + 4);
                const ull r = cur[j];
                const ull w0d = dup2(w4.x), w1d = dup2(w4.y);
                const ull w2d = dup2(w4.z), w3d = dup2(w4.w);
                const ull rv0 = fmul2(dup2(vv.x), r);
                const ull rv1 = fmul2(dup2(vv.y), r);
                acc[0]  = ffma2(w0d, r,   acc[0]);
                acc[1]  = ffma2(w0d, rv0, acc[1]);
                acc[2]  = ffma2(w0d, rv1, acc[2]);
                acc[3]  = ffma2(w1d, r,   acc[3]);
                acc[4]  = ffma2(w1d, rv0, acc[4]);
                acc[5]  = ffma2(w1d, rv1, acc[5]);
                acc[6]  = ffma2(w2d, r,   acc[6]);
                acc[7]  = ffma2(w2d, rv0, acc[7]);
                acc[8]  = ffma2(w2d, rv1, acc[8]);
                acc[9]  = ffma2(w3d, r,   acc[9]);
                acc[10] = ffma2(w3d, rv0, acc[10]);
                acc[11] = ffma2(w3d, rv1, acc[11]);
            }
        }

        // partials: part[sl][row][b]
        {
            float* pb = part + sl * 768 + lane * 2;
#pragma unroll
            for (int row = 0; row < 12; ++row) *(ull*)(pb + row * 64) = acc[row];
        }
        __syncthreads();

        // epilogue: threads 0..255 reduce 16 slices for their (g, b)
        if (tid < 256) {
            float y0 = 0.f, y1 = 0.f, y2 = 0.f;
            const float* q = part + eg * 192 + eb;
#pragma unroll
            for (int s = 0; s < 16; ++s) {
                y0 += q[s * 768];
                y1 += q[s * 768 + 64];
                y2 += q[s * 768 + 128];
            }
            v = ONEMA * v + ALPHA * (y0 + s0 * u0 * y1 + s1 * u1 * y2 + xi);
            const float r = tanhf(v);
            g_rbuf[(size_t)(t + 1) * (HDIM * BATCH) + (g0 + eg) * BATCH + eb] = r;
            if (t == T_STEPS - 1 && out_size >= BATCH * T_STEPS + BATCH * HDIM)
                dout[BATCH * T_STEPS + eb * HDIM + (g0 + eg)] = v;  // vT
        }
        if (t < T_STEPS - 1) grid_barrier();
    }
}

// ---------------- k_out: y[b,t] = tanh(v_{t+1}) @ w_out + b_out -------------
__global__ void __launch_bounds__(256, 1) k_out(const float* __restrict__ wout,
                                                const float* __restrict__ bout,
                                                float* __restrict__ dout,
                                                int out_size) {
    __shared__ float w_sh[HDIM];
    const int tid = threadIdx.x;
    w_sh[tid] = wout[tid];
    w_sh[tid + 256] = wout[tid + 256];
    __syncthreads();
    int gid = blockIdx.x * 256 + tid;
    int b = gid & 63, t = gid >> 6;
    const float* rp = g_rbuf + (size_t)(t + 1) * (HDIM * BATCH) + b;
    float acc = bout[0];
#pragma unroll 8
    for (int g = 0; g < HDIM; ++g) acc = fmaf(rp[g * BATCH], w_sh[g], acc);
    int o = b * T_STEPS + t;
    if (o < out_size) dout[o] = acc;
}

// ---------------- launch -----------------------------------------------------
extern "C" void kernel_launch(void* const* d_in, const int* in_sizes, int n_in,
                              void* d_out, int out_size) {
    const float* x    = (const float*)d_in[0];
    const float* win  = (const float*)d_in[1];
    const float* wrec = (const float*)d_in[2];
    const float* brec = (const float*)d_in[3];
    const float* wout = (const float*)d_in[4];
    const float* bout = (const float*)d_in[5];
    const float* wzz  = (const float*)d_in[6];
    const float* bzz  = (const float*)d_in[7];
    const float* Bz   = (const float*)d_in[8];
    const float* M    = (const float*)d_in[9];
    const float* c    = (const float*)d_in[10];
    const float* U    = (const float*)d_in[11];
    const float* V    = (const float*)d_in[12];
    float* out = (float*)d_out;

    cudaFuncSetAttribute(k_xin,  cudaFuncAttributeMaxDynamicSharedMemorySize, 16384 * 4);
    cudaFuncSetAttribute(k_xz,   cudaFuncAttributeMaxDynamicSharedMemorySize, 12288 * 4);
    cudaFuncSetAttribute(k_main, cudaFuncAttributeMaxDynamicSharedMemorySize, 16384 * 4);

    k_xz<<<T_STEPS, 64, 12288 * 4>>>(x, Bz, bzz);
    k_zscan<<<BATCH, 32>>>(wzz, M, c, out, out_size);
    k_xin<<<dim3(T_STEPS, HDIM / 64), 128, 16384 * 4>>>(x, win, brec);
    k_main<<<GRID_MAIN, 512, 16384 * 4>>>(wrec, V, U, out, out_size);
    k_out<<<(BATCH * T_STEPS) / 256, 256>>>(wout, bout, out, out_size);
}